// round 12
// baseline (speedup 1.0000x reference)
#include <cuda_runtime.h>
#include <cuda_bf16.h>
#include <cstdint>

// PoseDisentangler: bone_len + bone_dir from H36M skeleton.
// pose_3d: (B=128, N=4096, J=17, 3) fp32, row of 51 floats per (b,n).
// out: [bone_len (B*N*16)] ++ [bone_dir (B*N*48)]
//
// R12: 2 threads/row (8 bones each; joint sets 0-8 / 8-16 -> only 1.06x LDS
// redundancy vs 1.9x for 4 thr/row), 64 rows / 128 threads (2x ILP/phase,
// barrier stays 128 wide), smem transpose for coalesced stores, rsqrt-only.

#define ROWS 64                 // rows per block
#define THREADS 128
#define ROW_FLOATS 51           // 17 joints * 3
#define NB 16                   // bones
#define IN_F4 (ROWS * ROW_FLOATS / 4)   // 816 float4 per block
#define DIR_STRIDE 52           // padded dir row stride (floats)

// PARENT[j] packed 4 bits per bone: {0,1,2,0,4,5,0,7,8,9,8,11,12,8,14,15}
#define PARENT_PACK 0xFE8CB89870540210ULL
__device__ __forceinline__ int parent_of(int j) {
    return (int)((PARENT_PACK >> (j * 4)) & 15ULL);
}

__global__ __launch_bounds__(THREADS, 7)
void pose_bones_kernel(const float* __restrict__ in,
                       float* __restrict__ len_out,
                       float* __restrict__ dir_out)
{
    __shared__ float s_in[ROWS * ROW_FLOATS];      // 13056 B
    __shared__ float s_len[ROWS * NB];             //  4096 B
    __shared__ float s_dir[ROWS * DIR_STRIDE];     // 13312 B

    const int tid = threadIdx.x;

    // Stage input: 816 float4, coalesced (block base 13056B*blockIdx, 128B-aligned).
    {
        const float4* __restrict__ gin =
            reinterpret_cast<const float4*>(in) + (size_t)blockIdx.x * IN_F4;
        float4* s4 = reinterpret_cast<float4*>(s_in);
        #pragma unroll
        for (int k = 0; k < 7; ++k) {
            int idx = tid + k * THREADS;
            if (idx < IN_F4)                       // 816 = 6*128 + 48
                s4[idx] = gin[idx];
        }
    }
    __syncthreads();

    // Compute: thread (row = tid>>1, h = tid&1) does bones 8h..8h+7, once each.
    {
        const int row = tid >> 1;
        const int h   = tid & 1;
        const float* __restrict__ p = s_in + row * ROW_FLOATS;
        const int j0  = h * 8;

        float l[8];
        float d[24];
        #pragma unroll
        for (int jj = 0; jj < 8; ++jj) {
            const int j  = j0 + jj;
            const int ch = (j + 1) * 3;
            const int pa = parent_of(j) * 3;
            float vx = p[ch + 0] - p[pa + 0];
            float vy = p[ch + 1] - p[pa + 1];
            float vz = p[ch + 2] - p[pa + 2];
            float ss  = fmaxf(vx * vx + vy * vy + vz * vz, 1e-30f);
            float inv = rsqrtf(ss);                // single MUFU, ~2ulp
            l[jj]          = ss * inv;             // == sqrt(ss)
            d[jj * 3 + 0]  = vx * inv;
            d[jj * 3 + 1]  = vy * inv;
            d[jj * 3 + 2]  = vz * inv;
        }

        // len: 8 floats at s_len[row*16 + 8h] (16B aligned)
        float4* slp = reinterpret_cast<float4*>(s_len + row * NB + h * 8);
        slp[0] = make_float4(l[0], l[1], l[2], l[3]);
        slp[1] = make_float4(l[4], l[5], l[6], l[7]);
        // dir: 24 floats at s_dir[row*52 + 24h] (16B aligned)
        float4* sd = reinterpret_cast<float4*>(s_dir + row * DIR_STRIDE + h * 24);
        #pragma unroll
        for (int k = 0; k < 6; ++k)
            sd[k] = make_float4(d[4*k+0], d[4*k+1], d[4*k+2], d[4*k+3]);
    }
    __syncthreads();

    // Coalesced readback -> global.
    // len: block region = 64*16 floats = 256 float4, contiguous. 2 per thread.
    {
        const float4* sl4 = reinterpret_cast<const float4*>(s_len);
        float4* __restrict__ lo =
            reinterpret_cast<float4*>(len_out) + (size_t)blockIdx.x * (ROWS * NB / 4);
        lo[tid]           = sl4[tid];
        lo[tid + THREADS] = sl4[tid + THREADS];
    }
    // dir: block region = 64*48 floats = 768 float4, contiguous. 6 per thread.
    // smem f4 index for global f4 g: row = g/12 -> g + row (row stride 13 f4).
    {
        const float4* sd4 = reinterpret_cast<const float4*>(s_dir);
        float4* __restrict__ dd =
            reinterpret_cast<float4*>(dir_out) + (size_t)blockIdx.x * (ROWS * NB * 3 / 4);
        #pragma unroll
        for (int k = 0; k < 6; ++k) {
            int g = tid + k * THREADS;             // 0..767
            int r = g / 12;
            dd[g] = sd4[g + r];
        }
    }
}

extern "C" void kernel_launch(void* const* d_in, const int* in_sizes, int n_in,
                              void* d_out, int out_size)
{
    const float* in = (const float*)d_in[0];
    const int rows = in_sizes[0] / ROW_FLOATS;         // B*N = 524288

    float* len_out = (float*)d_out;
    float* dir_out = len_out + (size_t)rows * NB;

    const int blocks = rows / ROWS;                    // exact: 8192
    pose_bones_kernel<<<blocks, THREADS>>>(in, len_out, dir_out);
}

// round 13
// speedup vs baseline: 1.1489x; 1.1489x over previous
#include <cuda_runtime.h>
#include <cuda_bf16.h>
#include <cstdint>

// PoseDisentangler: bone_len + bone_dir from H36M skeleton.
// pose_3d: (B=128, N=4096, J=17, 3) fp32, row of 51 floats per (b,n).
// out: [bone_len (B*N*16)] ++ [bone_dir (B*N*48)]
//
// R13: TMA bulk copies for BOTH input (global->smem, mbarrier) and output
// (smem->global, bulk_group). LSU only does compute LDS + result STS.
// Results staged UNPADDED in exact output layout (f4 STS is conflict-free
// for the 4-thread/row assignment), so bulk stores are straight memcpys.

#define ROWS 32
#define THREADS 128
#define ROW_FLOATS 51
#define NB 16
#define IN_BYTES  (ROWS * ROW_FLOATS * 4)   // 6528
#define LEN_BYTES (ROWS * NB * 4)           // 2048
#define DIR_BYTES (ROWS * NB * 3 * 4)       // 6144

// PARENT[j] packed 4 bits per bone: {0,1,2,0,4,5,0,7,8,9,8,11,12,8,14,15}
#define PARENT_PACK 0xFE8CB89870540210ULL
__device__ __forceinline__ int parent_of(int j) {
    return (int)((PARENT_PACK >> (j * 4)) & 15ULL);
}

__device__ __forceinline__ uint32_t smem_u32(const void* p) {
    uint32_t a;
    asm("{ .reg .u64 t; cvta.to.shared.u64 t, %1; cvt.u32.u64 %0, t; }"
        : "=r"(a) : "l"(p));
    return a;
}

__global__ __launch_bounds__(THREADS)
void pose_bones_kernel(const float* __restrict__ in,
                       float* __restrict__ len_out,
                       float* __restrict__ dir_out)
{
    __shared__ alignas(16) float s_in[ROWS * ROW_FLOATS];
    __shared__ alignas(16) float s_len[ROWS * NB];
    __shared__ alignas(16) float s_dir[ROWS * NB * 3];
    __shared__ alignas(8)  unsigned long long mbar;

    const int tid = threadIdx.x;
    const uint32_t mb = smem_u32(&mbar);

    if (tid == 0) {
        asm volatile("mbarrier.init.shared.b64 [%0], 1;" :: "r"(mb) : "memory");
    }
    __syncthreads();

    // TMA bulk load: global -> smem (no LSU wavefronts)
    if (tid == 0) {
        const char* src = reinterpret_cast<const char*>(in) + (size_t)blockIdx.x * IN_BYTES;
        asm volatile("mbarrier.arrive.expect_tx.shared.b64 _, [%0], %1;"
                     :: "r"(mb), "r"((uint32_t)IN_BYTES) : "memory");
        asm volatile("cp.async.bulk.shared::cta.global.mbarrier::complete_tx::bytes "
                     "[%0], [%1], %2, [%3];"
                     :: "r"(smem_u32(s_in)), "l"(src), "r"((uint32_t)IN_BYTES), "r"(mb)
                     : "memory");
    }

    // Wait for the load (phase 0; mbarrier is re-inited every launch)
    {
        uint32_t done;
        asm volatile(
            "{\n\t.reg .pred p;\n\t"
            "mbarrier.try_wait.parity.acquire.cta.shared::cta.b64 p, [%1], 0;\n\t"
            "selp.b32 %0, 1, 0, p;\n\t}"
            : "=r"(done) : "r"(mb) : "memory");
        if (!done) {
            asm volatile(
                "{\n\t.reg .pred P1;\n\t"
                "WL_%=:\n\t"
                "mbarrier.try_wait.parity.acquire.cta.shared::cta.b64 P1, [%0], 0, 0x989680;\n\t"
                "@P1 bra.uni WD_%=;\n\t"
                "bra.uni WL_%=;\n\t"
                "WD_%=:\n\t}"
                :: "r"(mb) : "memory");
        }
    }

    // Compute: thread (row = tid>>2, q = tid&3) does bones 4q..4q+3.
    {
        const int row = tid >> 2;
        const int q   = tid & 3;
        const float* __restrict__ p = s_in + row * ROW_FLOATS;

        float l[4];
        float d[12];
        #pragma unroll
        for (int jj = 0; jj < 4; ++jj) {
            const int j  = q * 4 + jj;
            const int ch = (j + 1) * 3;
            const int pa = parent_of(j) * 3;
            float vx = p[ch + 0] - p[pa + 0];
            float vy = p[ch + 1] - p[pa + 1];
            float vz = p[ch + 2] - p[pa + 2];
            float ss  = fmaxf(vx * vx + vy * vy + vz * vz, 1e-30f);
            float inv = rsqrtf(ss);
            l[jj]         = ss * inv;              // == sqrt(ss)
            d[jj * 3 + 0] = vx * inv;
            d[jj * 3 + 1] = vy * inv;
            d[jj * 3 + 2] = vz * inv;
        }

        // Unpadded, exact output layout. Conflict-free f4 STS (see header note).
        *reinterpret_cast<float4*>(s_len + row * NB + q * 4) =
            make_float4(l[0], l[1], l[2], l[3]);
        float4* sd = reinterpret_cast<float4*>(s_dir + row * (NB * 3) + q * 12);
        sd[0] = make_float4(d[0], d[1], d[2],  d[3]);
        sd[1] = make_float4(d[4], d[5], d[6],  d[7]);
        sd[2] = make_float4(d[8], d[9], d[10], d[11]);
    }
    __syncthreads();

    // TMA bulk stores: smem -> global (no LSU wavefronts), then drain.
    if (tid == 0) {
        asm volatile("fence.proxy.async.shared::cta;" ::: "memory");
        char* dl = reinterpret_cast<char*>(len_out) + (size_t)blockIdx.x * LEN_BYTES;
        char* dd = reinterpret_cast<char*>(dir_out) + (size_t)blockIdx.x * DIR_BYTES;
        asm volatile("cp.async.bulk.global.shared::cta.bulk_group [%0], [%1], %2;"
                     :: "l"(dl), "r"(smem_u32(s_len)), "r"((uint32_t)LEN_BYTES) : "memory");
        asm volatile("cp.async.bulk.global.shared::cta.bulk_group [%0], [%1], %2;"
                     :: "l"(dd), "r"(smem_u32(s_dir)), "r"((uint32_t)DIR_BYTES) : "memory");
        asm volatile("cp.async.bulk.commit_group;" ::: "memory");
        asm volatile("cp.async.bulk.wait_group 0;" ::: "memory");
    }
}

extern "C" void kernel_launch(void* const* d_in, const int* in_sizes, int n_in,
                              void* d_out, int out_size)
{
    const float* in = (const float*)d_in[0];
    const int rows = in_sizes[0] / ROW_FLOATS;         // B*N = 524288

    float* len_out = (float*)d_out;
    float* dir_out = len_out + (size_t)rows * NB;

    const int blocks = rows / ROWS;                    // exact: 16384
    pose_bones_kernel<<<blocks, THREADS>>>(in, len_out, dir_out);
}

// round 14
// speedup vs baseline: 1.2061x; 1.0498x over previous
#include <cuda_runtime.h>
#include <cuda_bf16.h>
#include <cstdint>

// PoseDisentangler: bone_len + bone_dir from H36M skeleton.
// pose_3d: (B=128, N=4096, J=17, 3) fp32, row of 51 floats per (b,n).
// out: [bone_len (B*N*16)] ++ [bone_dir (B*N*48)]
//
// R14 = R13 (TMA bulk in/out, LSU only for compute) with doubled tile:
// 64 rows / 256 threads -> half the CTAs (overhead/2), 2x TMA transfer
// sizes, 7 CTAs/SM = 87.5% occupancy. Result STS stays unpadded &
// conflict-free (8-lane phases cover all 32 banks once).

#define ROWS 64
#define THREADS 256
#define ROW_FLOATS 51
#define NB 16
#define IN_BYTES  (ROWS * ROW_FLOATS * 4)   // 13056
#define LEN_BYTES (ROWS * NB * 4)           // 4096
#define DIR_BYTES (ROWS * NB * 3 * 4)       // 12288

// PARENT[j] packed 4 bits per bone: {0,1,2,0,4,5,0,7,8,9,8,11,12,8,14,15}
#define PARENT_PACK 0xFE8CB89870540210ULL
__device__ __forceinline__ int parent_of(int j) {
    return (int)((PARENT_PACK >> (j * 4)) & 15ULL);
}

__device__ __forceinline__ uint32_t smem_u32(const void* p) {
    uint32_t a;
    asm("{ .reg .u64 t; cvta.to.shared.u64 t, %1; cvt.u32.u64 %0, t; }"
        : "=r"(a) : "l"(p));
    return a;
}

__global__ __launch_bounds__(THREADS, 7)
void pose_bones_kernel(const float* __restrict__ in,
                       float* __restrict__ len_out,
                       float* __restrict__ dir_out)
{
    __shared__ alignas(16) float s_in[ROWS * ROW_FLOATS];
    __shared__ alignas(16) float s_len[ROWS * NB];
    __shared__ alignas(16) float s_dir[ROWS * NB * 3];
    __shared__ alignas(8)  unsigned long long mbar;

    const int tid = threadIdx.x;
    const uint32_t mb = smem_u32(&mbar);

    if (tid == 0) {
        asm volatile("mbarrier.init.shared.b64 [%0], 1;" :: "r"(mb) : "memory");
    }
    __syncthreads();

    // TMA bulk load: global -> smem (no LSU wavefronts)
    if (tid == 0) {
        const char* src = reinterpret_cast<const char*>(in) + (size_t)blockIdx.x * IN_BYTES;
        asm volatile("mbarrier.arrive.expect_tx.shared.b64 _, [%0], %1;"
                     :: "r"(mb), "r"((uint32_t)IN_BYTES) : "memory");
        asm volatile("cp.async.bulk.shared::cta.global.mbarrier::complete_tx::bytes "
                     "[%0], [%1], %2, [%3];"
                     :: "r"(smem_u32(s_in)), "l"(src), "r"((uint32_t)IN_BYTES), "r"(mb)
                     : "memory");
    }

    // Wait for the load (phase 0; mbarrier re-inited every launch)
    {
        uint32_t done;
        asm volatile(
            "{\n\t.reg .pred p;\n\t"
            "mbarrier.try_wait.parity.acquire.cta.shared::cta.b64 p, [%1], 0;\n\t"
            "selp.b32 %0, 1, 0, p;\n\t}"
            : "=r"(done) : "r"(mb) : "memory");
        if (!done) {
            asm volatile(
                "{\n\t.reg .pred P1;\n\t"
                "WL_%=:\n\t"
                "mbarrier.try_wait.parity.acquire.cta.shared::cta.b64 P1, [%0], 0, 0x989680;\n\t"
                "@P1 bra.uni WD_%=;\n\t"
                "bra.uni WL_%=;\n\t"
                "WD_%=:\n\t}"
                :: "r"(mb) : "memory");
        }
    }

    // Compute: thread (row = tid>>2, q = tid&3) does bones 4q..4q+3.
    {
        const int row = tid >> 2;
        const int q   = tid & 3;
        const float* __restrict__ p = s_in + row * ROW_FLOATS;

        float l[4];
        float d[12];
        #pragma unroll
        for (int jj = 0; jj < 4; ++jj) {
            const int j  = q * 4 + jj;
            const int ch = (j + 1) * 3;
            const int pa = parent_of(j) * 3;
            float vx = p[ch + 0] - p[pa + 0];
            float vy = p[ch + 1] - p[pa + 1];
            float vz = p[ch + 2] - p[pa + 2];
            float ss  = fmaxf(vx * vx + vy * vy + vz * vz, 1e-30f);
            float inv = rsqrtf(ss);
            l[jj]         = ss * inv;              // == sqrt(ss)
            d[jj * 3 + 0] = vx * inv;
            d[jj * 3 + 1] = vy * inv;
            d[jj * 3 + 2] = vz * inv;
        }

        // Unpadded, exact output layout; conflict-free f4 STS.
        *reinterpret_cast<float4*>(s_len + row * NB + q * 4) =
            make_float4(l[0], l[1], l[2], l[3]);
        float4* sd = reinterpret_cast<float4*>(s_dir + row * (NB * 3) + q * 12);
        sd[0] = make_float4(d[0], d[1], d[2],  d[3]);
        sd[1] = make_float4(d[4], d[5], d[6],  d[7]);
        sd[2] = make_float4(d[8], d[9], d[10], d[11]);
    }
    __syncthreads();

    // TMA bulk stores: smem -> global, then drain before CTA exit.
    if (tid == 0) {
        asm volatile("fence.proxy.async.shared::cta;" ::: "memory");
        char* dl = reinterpret_cast<char*>(len_out) + (size_t)blockIdx.x * LEN_BYTES;
        char* dd = reinterpret_cast<char*>(dir_out) + (size_t)blockIdx.x * DIR_BYTES;
        asm volatile("cp.async.bulk.global.shared::cta.bulk_group [%0], [%1], %2;"
                     :: "l"(dl), "r"(smem_u32(s_len)), "r"((uint32_t)LEN_BYTES) : "memory");
        asm volatile("cp.async.bulk.global.shared::cta.bulk_group [%0], [%1], %2;"
                     :: "l"(dd), "r"(smem_u32(s_dir)), "r"((uint32_t)DIR_BYTES) : "memory");
        asm volatile("cp.async.bulk.commit_group;" ::: "memory");
        asm volatile("cp.async.bulk.wait_group 0;" ::: "memory");
    }
}

extern "C" void kernel_launch(void* const* d_in, const int* in_sizes, int n_in,
                              void* d_out, int out_size)
{
    const float* in = (const float*)d_in[0];
    const int rows = in_sizes[0] / ROW_FLOATS;         // B*N = 524288

    float* len_out = (float*)d_out;
    float* dir_out = len_out + (size_t)rows * NB;

    const int blocks = rows / ROWS;                    // exact: 8192
    pose_bones_kernel<<<blocks, THREADS>>>(in, len_out, dir_out);
}